// round 11
// baseline (speedup 1.0000x reference)
#include <cuda_runtime.h>
#include <cuda_bf16.h>
#include <math.h>
#include <stdint.h>

#define DIMN 1024
#define SEQ 4096
#define BATCH 4
#define HEADS 16
#define DHN 64
#define KPROJ 64
#define MLPD 4096
#define EPSV 1e-5f
#define ROWS (BATCH*SEQ)

// ---------------- scratch (static device globals; allocation-free) ----------------
__device__ float g_xn[ROWS*DIMN];
__device__ float g_x2[ROWS*DIMN];
__device__ int8_t g_xn2q[ROWS*DIMN];                // [kc][ROWS][64] swizzled int8
__device__ __nv_bfloat16 g_hbuf[(size_t)ROWS*MLPD]; // plain [row][4096]
__device__ int8_t g_hq[(size_t)ROWS*MLPD];          // [kc][ROWS][64] swizzled int8
__device__ int8_t g_w1q[(size_t)DIMN*MLPD];
__device__ int8_t g_w2q[(size_t)MLPD*DIMN];
__device__ float g_as0[ROWS];
__device__ float g_as1[ROWS];
__device__ unsigned g_wm1[MLPD], g_wm2[DIMN];
__device__ float g_ws1[MLPD], g_ws2[DIMN];
__device__ float g_m[BATCH*DIMN];
__device__ float g_A[BATCH*DIMN];
__device__ float g_Ap[BATCH*DIMN];
__device__ float g_u[BATCH*DIMN*HEADS];
__device__ float g_G[BATCH*HEADS*DIMN];
__device__ float g_Bsum[KPROJ];
__device__ float g_Bpsum[KPROJ];

// ---------------- helpers ----------------
__device__ __forceinline__ uint32_t smem_u32(const void* p){
    return (uint32_t)__cvta_generic_to_shared(p);
}
__device__ __forceinline__ void ldsm_x4(uint32_t &r0,uint32_t &r1,uint32_t &r2,uint32_t &r3, uint32_t a){
    asm volatile("ldmatrix.sync.aligned.m8n8.x4.shared.b16 {%0,%1,%2,%3}, [%4];\n"
        : "=r"(r0),"=r"(r1),"=r"(r2),"=r"(r3) : "r"(a));
}
__device__ __forceinline__ uint32_t lds32(uint32_t a){
    uint32_t v; asm volatile("ld.shared.b32 %0, [%1];" : "=r"(v) : "r"(a)); return v;
}
__device__ __forceinline__ void mma_s8(int c[4], uint32_t a0,uint32_t a1,uint32_t a2,uint32_t a3,
                                       uint32_t b0,uint32_t b1){
    asm volatile("mma.sync.aligned.m16n8k32.row.col.s32.s8.s8.s32 "
        "{%0,%1,%2,%3},{%4,%5,%6,%7},{%8,%9},{%0,%1,%2,%3};\n"
        : "+r"(c[0]),"+r"(c[1]),"+r"(c[2]),"+r"(c[3])
        : "r"(a0),"r"(a1),"r"(a2),"r"(a3),"r"(b0),"r"(b1));
}
__device__ __forceinline__ float gelu_exact(float v){
    return 0.5f*v*(1.0f+erff(v*0.70710678118654752f));
}
__device__ __forceinline__ int q8(float v, float inv){
    int q = __float2int_rn(v*inv);
    return max(-127, min(127, q));
}
__device__ __forceinline__ void mbar_init(uint32_t mbar, uint32_t cnt){
    asm volatile("mbarrier.init.shared.b64 [%0], %1;" :: "r"(mbar), "r"(cnt) : "memory");
}
__device__ __forceinline__ void mbar_expect_tx(uint32_t mbar, uint32_t bytes){
    asm volatile("mbarrier.arrive.expect_tx.shared.b64 _, [%0], %1;"
        :: "r"(mbar), "r"(bytes) : "memory");
}
__device__ __forceinline__ void bulk_g2s(uint32_t dst, const void* src, uint32_t bytes, uint32_t mbar){
    asm volatile("cp.async.bulk.shared::cluster.global.mbarrier::complete_tx::bytes [%0], [%1], %2, [%3];"
        :: "r"(dst), "l"(src), "r"(bytes), "r"(mbar) : "memory");
}
__device__ __forceinline__ void mbar_wait(uint32_t mbar, uint32_t parity){
    asm volatile("{\n\t.reg .pred P;\n"
        "WLP%=:\n\tmbarrier.try_wait.parity.acquire.cta.shared::cta.b64 P, [%0], %1, 0x989680;\n"
        "\t@P bra WDN%=;\n\tbra WLP%=;\nWDN%=:\n\t}"
        :: "r"(mbar), "r"(parity) : "memory");
}
#define FENCE_ASYNC() asm volatile("fence.proxy.async.shared::cta;" ::: "memory")

// ---------------- small kernels ----------------
__global__ void zero_small_kernel(){
    int i = blockIdx.x*256 + threadIdx.x;
    if (i < BATCH*DIMN) g_m[i] = 0.f;
    if (i < KPROJ){ g_Bsum[i]=0.f; g_Bpsum[i]=0.f; }
    if (i < MLPD) g_wm1[i] = 0u;
    if (i < DIMN) g_wm2[i] = 0u;
}

template<int M>
__global__ __launch_bounds__(256) void colmax_kernel(const float* __restrict__ W, int Kd, int Nd){
    int n = blockIdx.x*256 + threadIdx.x;
    int kn = Kd >> 3;
    int k0 = blockIdx.y * kn;
    float mx = 1e-12f;
    for (int k=k0; k<k0+kn; k++) mx = fmaxf(mx, fabsf(W[(size_t)k*Nd + n]));
    atomicMax(M==0 ? &g_wm1[n] : &g_wm2[n], __float_as_uint(mx));
}

__global__ void wscale_kernel(){
    int i = blockIdx.x*256 + threadIdx.x;
    if (i < MLPD) g_ws1[i] = __uint_as_float(g_wm1[i]) * (1.f/127.f);
    if (i < DIMN) g_ws2[i] = __uint_as_float(g_wm2[i]) * (1.f/127.f);
}

// pack W [Kd][Nd] fp32 -> fragment-order int8 [nb][kc][ks][n 128][32]
template<int M>
__global__ __launch_bounds__(256) void pack_w_kernel(const float* __restrict__ src, int Kd, int Nd){
    int t = blockIdx.x*256 + threadIdx.x;
    if (t >= Nd*(Kd>>4)) return;
    int n  = t % Nd;
    int kg = t / Nd;
    int kc = kg >> 2, ksh = kg & 3;
    int nb = n >> 7, nl = n & 127;
    int KCn = Kd >> 6;
    float inv = 1.f / (M==0 ? g_ws1[n] : g_ws2[n]);
    unsigned w[4];
    #pragma unroll
    for (int j=0; j<4; j++){
        unsigned a = 0;
        #pragma unroll
        for (int b=0; b<4; b++){
            float v = src[(size_t)(kg*16 + j*4 + b)*Nd + n];
            a |= ((unsigned)(q8(v, inv) & 255)) << (b*8);
        }
        w[j] = a;
    }
    int8_t* dst = (M==0) ? g_w1q : g_w2q;
    size_t off = ((((size_t)(nb*KCn + kc)*2 + (ksh>>1))*128 + nl)*32) + (ksh&1)*16;
    *(uint4*)(dst + off) = make_uint4(w[0], w[1], w[2], w[3]);
}

__global__ __launch_bounds__(256) void ln1_kernel(const float* __restrict__ x,
        const float* __restrict__ g, const float* __restrict__ b){
    int row = blockIdx.x; int tid = threadIdx.x;
    __shared__ float sred[512];
    float4 v = ((const float4*)(x + (size_t)row*DIMN))[tid];
    float s  = v.x+v.y+v.z+v.w;
    float sq = v.x*v.x+v.y*v.y+v.z*v.z+v.w*v.w;
    sred[tid]=s; sred[256+tid]=sq; __syncthreads();
    #pragma unroll
    for (int off=128; off; off>>=1){
        if (tid<off){ sred[tid]+=sred[tid+off]; sred[256+tid]+=sred[256+tid+off]; }
        __syncthreads();
    }
    float mu  = sred[0]*(1.0f/DIMN);
    float var = sred[256]*(1.0f/DIMN) - mu*mu;
    float rs  = rsqrtf(var + EPSV);
    float4 gv = ((const float4*)g)[tid];
    float4 bv = ((const float4*)b)[tid];
    float4 o;
    o.x=(v.x-mu)*rs*gv.x+bv.x; o.y=(v.y-mu)*rs*gv.y+bv.y;
    o.z=(v.z-mu)*rs*gv.z+bv.z; o.w=(v.w-mu)*rs*gv.w+bv.w;
    ((float4*)(g_xn + (size_t)row*DIMN))[tid] = o;
}

__global__ void colsum_xn_kernel(){
    int b = blockIdx.x, chunk = blockIdx.y, j = threadIdx.x;
    const float* base = g_xn + ((size_t)(b*SEQ + chunk*128))*DIMN + j;
    float acc = 0.f;
    #pragma unroll 4
    for (int s=0; s<128; s++) acc += base[(size_t)s*DIMN];
    atomicAdd(&g_m[b*DIMN + j], acc);
}

__global__ void colsum_ef_kernel(const float* __restrict__ E, const float* __restrict__ Fm){
    const float* src = blockIdx.x ? Fm : E;
    float* dst = blockIdx.x ? g_Bpsum : g_Bsum;
    int kk = threadIdx.x;
    int s0 = blockIdx.y*256;
    float acc = 0.f;
    for (int s=0; s<256; s++) acc += src[(size_t)(s0+s)*KPROJ + kk];
    atomicAdd(&dst[kk], acc);
}

__global__ __launch_bounds__(256) void gemv_AAp_kernel(const float* __restrict__ Wk,
        const float* __restrict__ Wv){
    int b = blockIdx.y;
    int col = blockIdx.x*256 + threadIdx.x;
    __shared__ float sm[DIMN];
    for (int j=threadIdx.x; j<DIMN; j+=256) sm[j] = g_m[b*DIMN + j];
    __syncthreads();
    float ak=0.f, av=0.f;
    for (int j=0; j<DIMN; j++){
        float mj = sm[j];
        ak += mj * Wk[(size_t)j*DIMN + col];
        av += mj * Wv[(size_t)j*DIMN + col];
    }
    g_A [b*DIMN + col] = ak;
    g_Ap[b*DIMN + col] = av;
}

__global__ __launch_bounds__(256) void compute_u_kernel(const float* __restrict__ Wq){
    int b = blockIdx.x;
    __shared__ float sA[DIMN];
    for (int i=threadIdx.x; i<DIMN; i+=256) sA[i] = g_A[b*DIMN + i];
    __syncthreads();
    int j = blockIdx.y*16 + (threadIdx.x >> 4);
    int h = threadIdx.x & 15;
    const float* wrow = Wq + (size_t)j*DIMN + h*DHN;
    const float* av = sA + h*DHN;
    float acc = 0.f;
    #pragma unroll
    for (int d=0; d<DHN; d++) acc += wrow[d]*av[d];
    g_u[((size_t)b*DIMN + j)*HEADS + h] = acc;
}

__global__ __launch_bounds__(256) void compute_G_kernel(const float* __restrict__ Wo){
    int b = blockIdx.x, h = blockIdx.y;
    __shared__ float sa[DHN];
    if (threadIdx.x < DHN) sa[threadIdx.x] = g_Ap[b*DIMN + h*DHN + threadIdx.x];
    __syncthreads();
    float4 acc = {0.f,0.f,0.f,0.f};
    #pragma unroll 8
    for (int d=0; d<DHN; d++){
        float a = sa[d];
        float4 w = ((const float4*)(Wo + (size_t)(h*DHN + d)*DIMN))[threadIdx.x];
        acc.x += a*w.x; acc.y += a*w.y; acc.z += a*w.z; acc.w += a*w.w;
    }
    ((float4*)(g_G + (size_t)(b*HEADS + h)*DIMN))[threadIdx.x] = acc;
}

__global__ __launch_bounds__(256) void attn_apply_kernel(const float* __restrict__ x,
        const float* __restrict__ bo, const float* __restrict__ g2, const float* __restrict__ b2){
    int row = blockIdx.x;
    int b = row / SEQ;
    int tid = threadIdx.x;
    __shared__ float sxn[DIMN];
    __shared__ float sred[512];
    __shared__ float sw[HEADS];
    __shared__ float sB[KPROJ], sBp[KPROJ];

    ((float4*)sxn)[tid] = ((const float4*)(g_xn + (size_t)row*DIMN))[tid];
    if (tid < KPROJ){ sB[tid]=g_Bsum[tid]; sBp[tid]=g_Bpsum[tid]; }
    __syncthreads();

    int h = tid & 15, grp = tid >> 4;
    const float* ub = g_u + (size_t)b*DIMN*HEADS;
    float acc = 0.f;
    for (int jj = grp; jj < DIMN; jj += 16) acc += sxn[jj] * ub[(size_t)jj*HEADS + h];
    sred[tid] = acc;
    __syncthreads();
    #pragma unroll
    for (int off=128; off>=16; off>>=1){
        if (tid < off) sred[tid] += sred[tid+off];
        __syncthreads();
    }
    if (tid < HEADS){
        float c = sred[tid] * 0.125f;
        float mx = -INFINITY;
        #pragma unroll 8
        for (int k2=0; k2<KPROJ; k2++) mx = fmaxf(mx, c*sB[k2]);
        float se=0.f, sv=0.f;
        for (int k2=0; k2<KPROJ; k2++){
            float e = expf(c*sB[k2]-mx);
            se += e; sv += e*sBp[k2];
        }
        sw[tid] = sv/se;
    }
    __syncthreads();

    float4 xv = ((const float4*)(x + (size_t)row*DIMN))[tid];
    float4 bov = ((const float4*)bo)[tid];
    float4 o = {xv.x+bov.x, xv.y+bov.y, xv.z+bov.z, xv.w+bov.w};
    const float* Gb = g_G + (size_t)b*HEADS*DIMN;
    #pragma unroll
    for (int hh=0; hh<HEADS; hh++){
        float w = sw[hh];
        float4 g4 = ((const float4*)(Gb + (size_t)hh*DIMN))[tid];
        o.x += w*g4.x; o.y += w*g4.y; o.z += w*g4.z; o.w += w*g4.w;
    }
    ((float4*)(g_x2 + (size_t)row*DIMN))[tid] = o;

    float s  = o.x+o.y+o.z+o.w;
    float sq = o.x*o.x+o.y*o.y+o.z*o.z+o.w*o.w;
    sred[tid]=s; sred[256+tid]=sq; __syncthreads();
    #pragma unroll
    for (int off=128; off; off>>=1){
        if (tid<off){ sred[tid]+=sred[tid+off]; sred[256+tid]+=sred[256+tid+off]; }
        __syncthreads();
    }
    float mu  = sred[0]*(1.0f/DIMN);
    float var = sred[256]*(1.0f/DIMN) - mu*mu;
    float rs  = rsqrtf(var + EPSV);
    float4 gv = ((const float4*)g2)[tid];
    float4 b2v = ((const float4*)b2)[tid];
    float v0=(o.x-mu)*rs*gv.x+b2v.x, v1=(o.y-mu)*rs*gv.y+b2v.y;
    float v2=(o.z-mu)*rs*gv.z+b2v.z, v3=(o.w-mu)*rs*gv.w+b2v.w;

    __syncthreads();
    float mq = fmaxf(fmaxf(fabsf(v0),fabsf(v1)), fmaxf(fabsf(v2),fabsf(v3)));
    sred[tid] = mq; __syncthreads();
    #pragma unroll
    for (int off=128; off; off>>=1){
        if (tid<off) sred[tid] = fmaxf(sred[tid], sred[tid+off]);
        __syncthreads();
    }
    float mx2 = fmaxf(sred[0], 1e-12f);
    if (tid == 0) g_as0[row] = mx2 * (1.f/127.f);
    float inv = 127.f / mx2;

    int c0 = tid*4;
    int kc = c0 >> 6, cc = c0 & 63, g = cc >> 4;
    int gp = g ^ ((row>>1)&3);
    unsigned qw = (unsigned)(q8(v0,inv)&255) | ((unsigned)(q8(v1,inv)&255)<<8)
                | ((unsigned)(q8(v2,inv)&255)<<16) | ((unsigned)(q8(v3,inv)&255)<<24);
    *(unsigned*)((char*)g_xn2q + ((size_t)kc*ROWS + row)*64 + gp*16 + (cc & 15)) = qw;
}

__global__ __launch_bounds__(256) void quant_h_kernel(){
    int row = blockIdx.x; int tid = threadIdx.x;
    __shared__ float sred[256];
    const __nv_bfloat162* src = (const __nv_bfloat162*)(g_hbuf + (size_t)row*MLPD);
    float v[16];
    #pragma unroll
    for (int j=0; j<8; j++){
        float2 p = __bfloat1622float2(src[tid*8 + j]);
        v[j*2] = p.x; v[j*2+1] = p.y;
    }
    float mx = 0.f;
    #pragma unroll
    for (int j=0; j<16; j++) mx = fmaxf(mx, fabsf(v[j]));
    sred[tid] = mx; __syncthreads();
    #pragma unroll
    for (int off=128; off; off>>=1){
        if (tid<off) sred[tid] = fmaxf(sred[tid], sred[tid+off]);
        __syncthreads();
    }
    float m = fmaxf(sred[0], 1e-12f);
    if (tid == 0) g_as1[row] = m * (1.f/127.f);
    float inv = 127.f / m;
    unsigned w[4];
    #pragma unroll
    for (int j=0; j<4; j++){
        w[j] = (unsigned)(q8(v[j*4],inv)&255) | ((unsigned)(q8(v[j*4+1],inv)&255)<<8)
             | ((unsigned)(q8(v[j*4+2],inv)&255)<<16) | ((unsigned)(q8(v[j*4+3],inv)&255)<<24);
    }
    int kc = tid >> 2, g = tid & 3;
    int gp = g ^ ((row>>1)&3);
    *(uint4*)((char*)g_hq + ((size_t)kc*ROWS + row)*64 + gp*16) = make_uint4(w[0],w[1],w[2],w[3]);
}

// ---------- int8 IMMA GEMM: 128x128 tile, KC=64, bulk-copy 4-stage mbarrier ring ----------
#define GST 4
#define ATILE_B (128*64)
#define BTILE_B (64*128)
#define STAGE_B (ATILE_B + BTILE_B)
#define GEMM_SMEM (GST*STAGE_B + 64)

template<int MODE>
__global__ __launch_bounds__(256) void gemm_s8_kernel(const float* __restrict__ bias,
                                                      float* __restrict__ Cf){
    constexpr int N  = (MODE==0) ? MLPD : DIMN;
    constexpr int K  = (MODE==0) ? DIMN : MLPD;
    constexpr int nk = K / 64;
    const int8_t* Aq = (MODE==0) ? g_xn2q : g_hq;
    const int8_t* Bq = (MODE==0) ? g_w1q  : g_w2q;
    const float* as  = (MODE==0) ? g_as0  : g_as1;
    const float* ws  = (MODE==0) ? g_ws1  : g_ws2;

    extern __shared__ __align__(128) char smem[];
    uint32_t sbase = smem_u32(smem);
    uint32_t mbar  = sbase + GST*STAGE_B;
    int tid = threadIdx.x, warp = tid >> 5, lane = tid & 31;
    int bm = blockIdx.y * 128;
    int nb = blockIdx.x;
    int wm = (warp >> 2) * 64;
    int wn = (warp & 3) * 32;

    if (tid == 0){
        #pragma unroll
        for (int s=0; s<GST; s++) mbar_init(mbar + 8*s, 1);
        FENCE_ASYNC();
    }
    __syncthreads();

    auto fill = [&](int st, int kc){
        uint32_t dstA = sbase + st*STAGE_B;
        uint32_t mb = mbar + 8*st;
        mbar_expect_tx(mb, STAGE_B);
        bulk_g2s(dstA, Aq + ((size_t)kc*ROWS + bm)*64, ATILE_B, mb);
        bulk_g2s(dstA + ATILE_B, Bq + (size_t)(nb*nk + kc)*BTILE_B, BTILE_B, mb);
    };
    if (tid == 0){
        #pragma unroll
        for (int p=0; p<GST-1; p++) fill(p, p);
    }

    int acc[4][4][4];
    #pragma unroll
    for (int i=0;i<4;i++)
        #pragma unroll
        for (int j=0;j<4;j++)
            #pragma unroll
            for (int k=0;k<4;k++) acc[i][j][k]=0;

    for (int kt = 0; kt < nk; kt++){
        int cur = kt & (GST-1);
        __syncthreads();
        if (tid == 0 && kt + GST - 1 < nk) fill((kt + GST - 1) & (GST-1), kt + GST - 1);
        mbar_wait(mbar + 8*cur, (kt >> 2) & 1);

        uint32_t As = sbase + cur*STAGE_B;
        uint32_t Bs = As + ATILE_B;

        #pragma unroll
        for (int ks=0; ks<2; ks++){
            uint32_t af[4][4], bfr[4][2];
            #pragma unroll
            for (int mi=0; mi<4; mi++){
                int r = wm + mi*16 + (lane & 15);
                int g = ks*2 + (lane >> 4);
                int gp = g ^ ((r>>1)&3);
                ldsm_x4(af[mi][0],af[mi][1],af[mi][2],af[mi][3], As + r*64 + gp*16);
            }
            #pragma unroll
            for (int ni=0; ni<4; ni++){
                int n = wn + ni*8 + (lane >> 2);
                uint32_t base = Bs + ks*4096 + n*32 + (lane & 3)*4;
                bfr[ni][0] = lds32(base);
                bfr[ni][1] = lds32(base + 16);
            }
            #pragma unroll
            for (int mi=0; mi<4; mi++)
                #pragma unroll
                for (int ni=0; ni<4; ni++)
                    mma_s8(acc[mi][ni], af[mi][0],af[mi][1],af[mi][2],af[mi][3],
                           bfr[ni][0], bfr[ni][1]);
        }
    }

    // epilogue: dequant + bias (+gelu / +residual)
    #pragma unroll
    for (int mi=0; mi<4; mi++){
        int r0 = bm + wm + mi*16 + (lane >> 2);
        float sa0 = as[r0], sa8 = as[r0+8];
        #pragma unroll
        for (int ni=0; ni<4; ni++){
            int c = nb*128 + wn + ni*8 + (lane & 3)*2;
            float w0 = ws[c], w1 = ws[c+1];
            float bx = bias[c], by = bias[c+1];
            int* a = acc[mi][ni];
            if (MODE == 0){
                float v0 = gelu_exact((float)a[0]*sa0*w0 + bx);
                float v1 = gelu_exact((float)a[1]*sa0*w1 + by);
                float v2 = gelu_exact((float)a[2]*sa8*w0 + bx);
                float v3 = gelu_exact((float)a[3]*sa8*w1 + by);
                *(__nv_bfloat162*)(g_hbuf + (size_t)r0*N + c)     = __floats2bfloat162_rn(v0,v1);
                *(__nv_bfloat162*)(g_hbuf + (size_t)(r0+8)*N + c) = __floats2bfloat162_rn(v2,v3);
            } else {
                size_t o0 = (size_t)r0*N + c, o1 = (size_t)(r0+8)*N + c;
                float2 x0 = *(const float2*)(g_x2 + o0);
                float2 x1 = *(const float2*)(g_x2 + o1);
                *(float2*)(Cf + o0) = make_float2((float)a[0]*sa0*w0 + bx + x0.x,
                                                  (float)a[1]*sa0*w1 + by + x0.y);
                *(float2*)(Cf + o1) = make_float2((float)a[2]*sa8*w0 + bx + x1.x,
                                                  (float)a[3]*sa8*w1 + by + x1.y);
            }
        }
    }
}

// ---------------- launch ----------------
extern "C" void kernel_launch(void* const* d_in, const int* in_sizes, int n_in,
                              void* d_out, int out_size){
    const float* x     = (const float*)d_in[0];
    const float* Wq    = (const float*)d_in[1];
    const float* Wk    = (const float*)d_in[2];
    const float* Wv    = (const float*)d_in[3];
    const float* E     = (const float*)d_in[4];
    const float* Fm    = (const float*)d_in[5];
    const float* Wo    = (const float*)d_in[6];
    const float* bo    = (const float*)d_in[7];
    const float* ln1_g = (const float*)d_in[8];
    const float* ln1_b = (const float*)d_in[9];
    const float* ln2_g = (const float*)d_in[10];
    const float* ln2_b = (const float*)d_in[11];
    const float* W1    = (const float*)d_in[12];
    const float* b1    = (const float*)d_in[13];
    const float* W2    = (const float*)d_in[14];
    const float* b2    = (const float*)d_in[15];
    float* out = (float*)d_out;

    cudaFuncSetAttribute(gemm_s8_kernel<0>, cudaFuncAttributeMaxDynamicSharedMemorySize, GEMM_SMEM);
    cudaFuncSetAttribute(gemm_s8_kernel<1>, cudaFuncAttributeMaxDynamicSharedMemorySize, GEMM_SMEM);

    zero_small_kernel<<<16, 256>>>();
    colmax_kernel<0><<<dim3(MLPD/256, 8), 256>>>(W1, DIMN, MLPD);
    colmax_kernel<1><<<dim3(DIMN/256, 8), 256>>>(W2, MLPD, DIMN);
    wscale_kernel<<<16, 256>>>();
    pack_w_kernel<0><<<(MLPD*(DIMN/16) + 255)/256, 256>>>(W1, DIMN, MLPD);
    pack_w_kernel<1><<<(DIMN*(MLPD/16) + 255)/256, 256>>>(W2, MLPD, DIMN);

    ln1_kernel<<<ROWS, 256>>>(x, ln1_g, ln1_b);
    colsum_xn_kernel<<<dim3(BATCH, 32), 1024>>>();
    colsum_ef_kernel<<<dim3(2, 16), 64>>>(E, Fm);
    gemv_AAp_kernel<<<dim3(4, BATCH), 256>>>(Wk, Wv);
    compute_u_kernel<<<dim3(BATCH, 64), 256>>>(Wq);
    compute_G_kernel<<<dim3(BATCH, HEADS), 256>>>(Wo);
    attn_apply_kernel<<<ROWS, 256>>>(x, bo, ln2_g, ln2_b);

    gemm_s8_kernel<0><<<dim3(MLPD/128, ROWS/128), 256, GEMM_SMEM>>>(b1, nullptr);
    quant_h_kernel<<<ROWS, 256>>>();
    gemm_s8_kernel<1><<<dim3(DIMN/128, ROWS/128), 256, GEMM_SMEM>>>(b2, out);
}

// round 15
// speedup vs baseline: 1.7358x; 1.7358x over previous
#include <cuda_runtime.h>
#include <cuda_bf16.h>
#include <cuda_fp16.h>
#include <math.h>
#include <stdint.h>

#define DIMN 1024
#define SEQ 4096
#define BATCH 4
#define HEADS 16
#define DHN 64
#define KPROJ 64
#define MLPD 4096
#define EPSV 1e-5f
#define ROWS (BATCH*SEQ)

// ---------------- scratch (static device globals; allocation-free) ----------------
__device__ float g_xn[ROWS*DIMN];                   // LN1 output
__device__ float g_x2[ROWS*DIMN];                   // x + attn residual
// K-chunked, pre-swizzled activations: [kc][ROWS][64] fp16
__device__ __half g_xn2[ROWS*DIMN];
__device__ __half g_hbuf[(size_t)ROWS*MLPD];
// pre-packed, pre-swizzled weights: [nb][kc][64][128] fp16
__device__ __half g_w1p[DIMN*MLPD];
__device__ __half g_w2p[MLPD*DIMN];
__device__ float g_m[BATCH*DIMN];
__device__ float g_A[BATCH*DIMN];
__device__ float g_Ap[BATCH*DIMN];
__device__ float g_u[BATCH*DIMN*HEADS];
__device__ float g_G[BATCH*HEADS*DIMN];
__device__ float g_Bsum[KPROJ];
__device__ float g_Bpsum[KPROJ];

// ---------------- helpers ----------------
__device__ __forceinline__ uint32_t smem_u32(const void* p){
    return (uint32_t)__cvta_generic_to_shared(p);
}
__device__ __forceinline__ void ldsm_x4(uint32_t &r0,uint32_t &r1,uint32_t &r2,uint32_t &r3, uint32_t a){
    asm volatile("ldmatrix.sync.aligned.m8n8.x4.shared.b16 {%0,%1,%2,%3}, [%4];\n"
        : "=r"(r0),"=r"(r1),"=r"(r2),"=r"(r3) : "r"(a));
}
__device__ __forceinline__ void ldsm_x4_t(uint32_t &r0,uint32_t &r1,uint32_t &r2,uint32_t &r3, uint32_t a){
    asm volatile("ldmatrix.sync.aligned.m8n8.x4.trans.shared.b16 {%0,%1,%2,%3}, [%4];\n"
        : "=r"(r0),"=r"(r1),"=r"(r2),"=r"(r3) : "r"(a));
}
// f16-accumulate HMMA: D(f16x2 x2) = A(f16) * B(f16) + D
__device__ __forceinline__ void mma_f16acc(uint32_t &d0, uint32_t &d1,
                                           uint32_t a0,uint32_t a1,uint32_t a2,uint32_t a3,
                                           uint32_t b0,uint32_t b1){
    asm volatile("mma.sync.aligned.m16n8k16.row.col.f16.f16.f16.f16 "
        "{%0,%1},{%2,%3,%4,%5},{%6,%7},{%0,%1};\n"
        : "+r"(d0),"+r"(d1)
        : "r"(a0),"r"(a1),"r"(a2),"r"(a3),"r"(b0),"r"(b1));
}
__device__ __forceinline__ float gelu_exact(float v){
    return 0.5f*v*(1.0f+erff(v*0.70710678118654752f));
}
__device__ __forceinline__ void mbar_init(uint32_t mbar, uint32_t cnt){
    asm volatile("mbarrier.init.shared.b64 [%0], %1;" :: "r"(mbar), "r"(cnt) : "memory");
}
__device__ __forceinline__ void mbar_expect_tx(uint32_t mbar, uint32_t bytes){
    asm volatile("mbarrier.arrive.expect_tx.shared.b64 _, [%0], %1;"
        :: "r"(mbar), "r"(bytes) : "memory");
}
__device__ __forceinline__ void bulk_g2s(uint32_t dst, const void* src, uint32_t bytes, uint32_t mbar){
    asm volatile("cp.async.bulk.shared::cluster.global.mbarrier::complete_tx::bytes [%0], [%1], %2, [%3];"
        :: "r"(dst), "l"(src), "r"(bytes), "r"(mbar) : "memory");
}
__device__ __forceinline__ void mbar_wait(uint32_t mbar, uint32_t parity){
    asm volatile("{\n\t.reg .pred P;\n"
        "WLP%=:\n\tmbarrier.try_wait.parity.acquire.cta.shared::cta.b64 P, [%0], %1, 0x989680;\n"
        "\t@P bra WDN%=;\n\tbra WLP%=;\nWDN%=:\n\t}"
        :: "r"(mbar), "r"(parity) : "memory");
}
#define FENCE_ASYNC() asm volatile("fence.proxy.async.shared::cta;" ::: "memory")

// ---------------- small kernels ----------------
__global__ void zero_small_kernel(){
    int i = blockIdx.x*256 + threadIdx.x;
    if (i < BATCH*DIMN) g_m[i] = 0.f;
    if (i < KPROJ){ g_Bsum[i]=0.f; g_Bpsum[i]=0.f; }
}

__global__ __launch_bounds__(256) void ln1_kernel(const float* __restrict__ x,
        const float* __restrict__ g, const float* __restrict__ b){
    int row = blockIdx.x; int tid = threadIdx.x;
    __shared__ float sred[512];
    float4 v = ((const float4*)(x + (size_t)row*DIMN))[tid];
    float s  = v.x+v.y+v.z+v.w;
    float sq = v.x*v.x+v.y*v.y+v.z*v.z+v.w*v.w;
    sred[tid]=s; sred[256+tid]=sq; __syncthreads();
    #pragma unroll
    for (int off=128; off; off>>=1){
        if (tid<off){ sred[tid]+=sred[tid+off]; sred[256+tid]+=sred[256+tid+off]; }
        __syncthreads();
    }
    float mu  = sred[0]*(1.0f/DIMN);
    float var = sred[256]*(1.0f/DIMN) - mu*mu;
    float rs  = rsqrtf(var + EPSV);
    float4 gv = ((const float4*)g)[tid];
    float4 bv = ((const float4*)b)[tid];
    float4 o;
    o.x=(v.x-mu)*rs*gv.x+bv.x; o.y=(v.y-mu)*rs*gv.y+bv.y;
    o.z=(v.z-mu)*rs*gv.z+bv.z; o.w=(v.w-mu)*rs*gv.w+bv.w;
    ((float4*)(g_xn + (size_t)row*DIMN))[tid] = o;
}

__global__ void colsum_xn_kernel(){
    int b = blockIdx.x, chunk = blockIdx.y, j = threadIdx.x;
    const float* base = g_xn + ((size_t)(b*SEQ + chunk*128))*DIMN + j;
    float acc = 0.f;
    #pragma unroll 4
    for (int s=0; s<128; s++) acc += base[(size_t)s*DIMN];
    atomicAdd(&g_m[b*DIMN + j], acc);
}

__global__ void colsum_ef_kernel(const float* __restrict__ E, const float* __restrict__ Fm){
    const float* src = blockIdx.x ? Fm : E;
    float* dst = blockIdx.x ? g_Bpsum : g_Bsum;
    int kk = threadIdx.x;
    int s0 = blockIdx.y*256;
    float acc = 0.f;
    for (int s=0; s<256; s++) acc += src[(size_t)(s0+s)*KPROJ + kk];
    atomicAdd(&dst[kk], acc);
}

__global__ __launch_bounds__(256) void gemv_AAp_kernel(const float* __restrict__ Wk,
        const float* __restrict__ Wv){
    int b = blockIdx.y;
    int col = blockIdx.x*256 + threadIdx.x;
    __shared__ float sm[DIMN];
    for (int j=threadIdx.x; j<DIMN; j+=256) sm[j] = g_m[b*DIMN + j];
    __syncthreads();
    float ak=0.f, av=0.f;
    for (int j=0; j<DIMN; j++){
        float mj = sm[j];
        ak += mj * Wk[(size_t)j*DIMN + col];
        av += mj * Wv[(size_t)j*DIMN + col];
    }
    g_A [b*DIMN + col] = ak;
    g_Ap[b*DIMN + col] = av;
}

__global__ __launch_bounds__(256) void compute_u_kernel(const float* __restrict__ Wq){
    int b = blockIdx.x;
    __shared__ float sA[DIMN];
    for (int i=threadIdx.x; i<DIMN; i+=256) sA[i] = g_A[b*DIMN + i];
    __syncthreads();
    int j = blockIdx.y*16 + (threadIdx.x >> 4);
    int h = threadIdx.x & 15;
    const float* wrow = Wq + (size_t)j*DIMN + h*DHN;
    const float* av = sA + h*DHN;
    float acc = 0.f;
    #pragma unroll
    for (int d=0; d<DHN; d++) acc += wrow[d]*av[d];
    g_u[((size_t)b*DIMN + j)*HEADS + h] = acc;
}

__global__ __launch_bounds__(256) void compute_G_kernel(const float* __restrict__ Wo){
    int b = blockIdx.x, h = blockIdx.y;
    __shared__ float sa[DHN];
    if (threadIdx.x < DHN) sa[threadIdx.x] = g_Ap[b*DIMN + h*DHN + threadIdx.x];
    __syncthreads();
    float4 acc = {0.f,0.f,0.f,0.f};
    #pragma unroll 8
    for (int d=0; d<DHN; d++){
        float a = sa[d];
        float4 w = ((const float4*)(Wo + (size_t)(h*DHN + d)*DIMN))[threadIdx.x];
        acc.x += a*w.x; acc.y += a*w.y; acc.z += a*w.z; acc.w += a*w.w;
    }
    ((float4*)(g_G + (size_t)(b*HEADS + h)*DIMN))[threadIdx.x] = acc;
}

// fused attn + residual + LN2; writes xn2 fp16 in K-chunked swizzled layout
__global__ __launch_bounds__(256) void attn_apply_kernel(const float* __restrict__ x,
        const float* __restrict__ bo, const float* __restrict__ g2, const float* __restrict__ b2){
    int row = blockIdx.x;
    int b = row / SEQ;
    int tid = threadIdx.x;
    __shared__ float sxn[DIMN];
    __shared__ float sred[512];
    __shared__ float sw[HEADS];
    __shared__ float sB[KPROJ], sBp[KPROJ];

    ((float4*)sxn)[tid] = ((const float4*)(g_xn + (size_t)row*DIMN))[tid];
    if (tid < KPROJ){ sB[tid]=g_Bsum[tid]; sBp[tid]=g_Bpsum[tid]; }
    __syncthreads();

    int h = tid & 15, grp = tid >> 4;
    const float* ub = g_u + (size_t)b*DIMN*HEADS;
    float acc = 0.f;
    for (int jj = grp; jj < DIMN; jj += 16) acc += sxn[jj] * ub[(size_t)jj*HEADS + h];
    sred[tid] = acc;
    __syncthreads();
    #pragma unroll
    for (int off=128; off>=16; off>>=1){
        if (tid < off) sred[tid] += sred[tid+off];
        __syncthreads();
    }
    if (tid < HEADS){
        float c = sred[tid] * 0.125f;
        float mx = -INFINITY;
        #pragma unroll 8
        for (int k2=0; k2<KPROJ; k2++) mx = fmaxf(mx, c*sB[k2]);
        float se=0.f, sv=0.f;
        for (int k2=0; k2<KPROJ; k2++){
            float e = expf(c*sB[k2]-mx);
            se += e; sv += e*sBp[k2];
        }
        sw[tid] = sv/se;
    }
    __syncthreads();

    float4 xv = ((const float4*)(x + (size_t)row*DIMN))[tid];
    float4 bov = ((const float4*)bo)[tid];
    float4 o = {xv.x+bov.x, xv.y+bov.y, xv.z+bov.z, xv.w+bov.w};
    const float* Gb = g_G + (size_t)b*HEADS*DIMN;
    #pragma unroll
    for (int hh=0; hh<HEADS; hh++){
        float w = sw[hh];
        float4 g4 = ((const float4*)(Gb + (size_t)hh*DIMN))[tid];
        o.x += w*g4.x; o.y += w*g4.y; o.z += w*g4.z; o.w += w*g4.w;
    }
    ((float4*)(g_x2 + (size_t)row*DIMN))[tid] = o;

    float s  = o.x+o.y+o.z+o.w;
    float sq = o.x*o.x+o.y*o.y+o.z*o.z+o.w*o.w;
    sred[tid]=s; sred[256+tid]=sq; __syncthreads();
    #pragma unroll
    for (int off=128; off; off>>=1){
        if (tid<off){ sred[tid]+=sred[tid+off]; sred[256+tid]+=sred[256+tid+off]; }
        __syncthreads();
    }
    float mu  = sred[0]*(1.0f/DIMN);
    float var = sred[256]*(1.0f/DIMN) - mu*mu;
    float rs  = rsqrtf(var + EPSV);
    float4 gv = ((const float4*)g2)[tid];
    float4 b2v = ((const float4*)b2)[tid];
    float v0=(o.x-mu)*rs*gv.x+b2v.x, v1=(o.y-mu)*rs*gv.y+b2v.y;
    float v2=(o.z-mu)*rs*gv.z+b2v.z, v3=(o.w-mu)*rs*gv.w+b2v.w;

    // chunked + swizzled write
    int c0 = tid*4;
    int kc = c0 >> 6, cc = c0 & 63, g = cc >> 3;
    int gp = g ^ (row & 7);
    uint2 val;
    __half2 p0 = __floats2half2_rn(v0, v1);
    __half2 p1 = __floats2half2_rn(v2, v3);
    val.x = *(uint32_t*)&p0; val.y = *(uint32_t*)&p1;
    *(uint2*)((char*)g_xn2 + ((size_t)kc*ROWS + row)*128 + gp*16 + (cc & 7)*2) = val;
}

// pack W [K][N] fp32 -> [nb][kc][kr 0..63][128 cols swizzled] fp16
__global__ __launch_bounds__(256) void pack_w_kernel(const float* __restrict__ src,
        __half* __restrict__ dst, int Kdim, int Ndim){
    int t = blockIdx.x*256 + threadIdx.x;          // one 8-elem granule
    int KCn = Kdim >> 6;
    int g  = t & 15;
    int kr = (t >> 4) & 63;
    int rest = t >> 10;         // nb*KCn + kc
    int kc = rest % KCn;
    int nb = rest / KCn;
    if (nb >= (Ndim >> 7)) return;
    int k = kc*64 + kr;
    int n = nb*128 + g*8;
    const float* s = src + (size_t)k*Ndim + n;
    float4 v0 = *(const float4*)s;
    float4 v1 = *(const float4*)(s+4);
    int gp = (g & 8) | ((g & 7) ^ (kr & 7));
    __half2* d = (__half2*)(dst + ((((size_t)rest)*64 + kr)*128) + gp*8);
    d[0] = __floats2half2_rn(v0.x, v0.y);
    d[1] = __floats2half2_rn(v0.z, v0.w);
    d[2] = __floats2half2_rn(v1.x, v1.y);
    d[3] = __floats2half2_rn(v1.z, v1.w);
}

// ---------- fp16 mma GEMM, 128x128 tile, KC=64, bulk-copy 4-stage mbarrier ring ----------
// f16 accumulation inside each 64-deep chunk, f32 promotion per chunk
#define GST 4
#define KCHK 64
#define ATILE_B (128*128)              // 16 KB
#define BTILE_B (64*256)               // 16 KB
#define STAGE_B (ATILE_B + BTILE_B)    // 32 KB
#define GEMM_SMEM (GST*STAGE_B + 64)

template<int MODE>
__global__ __launch_bounds__(256,1) void gemm_bulk_kernel(const float* __restrict__ bias,
                                                          float* __restrict__ Cf){
    constexpr int N  = (MODE==0) ? MLPD : DIMN;
    constexpr int K  = (MODE==0) ? DIMN : MLPD;
    constexpr int nk = K / KCHK;
    const __half* Ach = (MODE==0) ? g_xn2 : g_hbuf;   // [kc][ROWS][64]
    const __half* Bpk = (MODE==0) ? g_w1p : g_w2p;    // [nb][kc][64][128]

    extern __shared__ __align__(128) char smem[];
    uint32_t sbase = smem_u32(smem);
    uint32_t mbar  = sbase + GST*STAGE_B;
    int tid = threadIdx.x, warp = tid >> 5, lane = tid & 31;
    int bm = blockIdx.y * 128;
    int nb = blockIdx.x;
    int wm = (warp >> 2) * 64;
    int wn = (warp & 3) * 32;

    if (tid == 0){
        #pragma unroll
        for (int s=0; s<GST; s++) mbar_init(mbar + 8*s, 1);
        FENCE_ASYNC();
    }
    __syncthreads();

    auto fill = [&](int st, int kc){
        uint32_t dstA = sbase + st*STAGE_B;
        uint32_t mb = mbar + 8*st;
        mbar_expect_tx(mb, STAGE_B);
        bulk_g2s(dstA, (const char*)Ach + ((size_t)kc*ROWS + bm)*128, ATILE_B, mb);
        bulk_g2s(dstA + ATILE_B, (const char*)Bpk + ((size_t)nb*nk + kc)*(size_t)BTILE_B, BTILE_B, mb);
    };

    if (tid == 0){
        #pragma unroll
        for (int p=0; p<GST-1; p++) fill(p, p);
    }

    float acc[4][4][4];
    #pragma unroll
    for (int i=0;i<4;i++)
        #pragma unroll
        for (int j=0;j<4;j++)
            #pragma unroll
            for (int k=0;k<4;k++) acc[i][j][k]=0.f;

    for (int kt = 0; kt < nk; kt++){
        int cur = kt & (GST-1);
        __syncthreads();
        if (tid == 0 && kt + GST - 1 < nk) fill((kt + GST - 1) & (GST-1), kt + GST - 1);
        mbar_wait(mbar + 8*cur, (kt >> 2) & 1);

        uint32_t As = sbase + cur*STAGE_B;
        uint32_t Bs = As + ATILE_B;

        // f16 chunk accumulators
        uint32_t hacc[4][4][2];
        #pragma unroll
        for (int i=0;i<4;i++)
            #pragma unroll
            for (int j=0;j<4;j++){ hacc[i][j][0]=0u; hacc[i][j][1]=0u; }

        #pragma unroll
        for (int ks=0; ks<4; ks++){
            uint32_t af[4][4], bfr[4][2];
            #pragma unroll
            for (int mi=0; mi<4; mi++){
                int r = wm + mi*16 + (lane & 15);
                int g = ks*2 + (lane >> 4);
                int gp = g ^ (r & 7);
                ldsm_x4(af[mi][0],af[mi][1],af[mi][2],af[mi][3],
                        As + r*128 + gp*16);
            }
            #pragma unroll
            for (int nj=0; nj<2; nj++){
                int r = ks*16 + (((lane>>3)&1) << 3) + (lane & 7);
                int c = wn + nj*16 + ((lane >> 4) << 3);
                int g = c >> 3;
                int gp = (g & 8) | ((g & 7) ^ (r & 7));
                uint32_t t0,t1,t2,t3;
                ldsm_x4_t(t0,t1,t2,t3, Bs + r*256 + gp*16);
                bfr[nj*2][0]=t0; bfr[nj*2][1]=t1;
                bfr[nj*2+1][0]=t2; bfr[nj*2+1][1]=t3;
            }
            #pragma unroll
            for (int mi=0; mi<4; mi++)
                #pragma unroll
                for (int ni=0; ni<4; ni++)
                    mma_f16acc(hacc[mi][ni][0], hacc[mi][ni][1],
                               af[mi][0],af[mi][1],af[mi][2],af[mi][3],
                               bfr[ni][0], bfr[ni][1]);
        }

        // promote chunk sums to f32
        #pragma unroll
        for (int mi=0; mi<4; mi++)
            #pragma unroll
            for (int ni=0; ni<4; ni++){
                float2 f0 = __half22float2(*(__half2*)&hacc[mi][ni][0]);
                float2 f1 = __half22float2(*(__half2*)&hacc[mi][ni][1]);
                acc[mi][ni][0] += f0.x; acc[mi][ni][1] += f0.y;
                acc[mi][ni][2] += f1.x; acc[mi][ni][3] += f1.y;
            }
    }

    // epilogue
    #pragma unroll
    for (int mi=0; mi<4; mi++){
        #pragma unroll
        for (int ni=0; ni<4; ni++){
            int r = bm + wm + mi*16 + (lane >> 2);
            int c = nb*128 + wn + ni*8 + (lane & 3)*2;
            float* a = acc[mi][ni];
            float bx = bias[c], by = bias[c+1];
            if (MODE == 0){
                float v0 = gelu_exact(a[0]+bx), v1 = gelu_exact(a[1]+by);
                float v2 = gelu_exact(a[2]+bx), v3 = gelu_exact(a[3]+by);
                int kc = c >> 6, cc = c & 63, g = cc >> 3;
                int gp = g ^ (r & 7);
                size_t base0 = ((size_t)kc*ROWS + r)*128 + gp*16 + (cc & 7)*2;
                __half2 p0 = __floats2half2_rn(v0, v1);
                __half2 p1 = __floats2half2_rn(v2, v3);
                *(__half2*)((char*)g_hbuf + base0)         = p0;
                *(__half2*)((char*)g_hbuf + base0 + 8*128) = p1;
            } else {
                size_t o0 = (size_t)r*N + c, o1 = (size_t)(r+8)*N + c;
                float2 r0 = *(const float2*)(g_x2 + o0);
                float2 r1 = *(const float2*)(g_x2 + o1);
                *(float2*)(Cf + o0) = make_float2(a[0]+bx+r0.x, a[1]+by+r0.y);
                *(float2*)(Cf + o1) = make_float2(a[2]+bx+r1.x, a[3]+by+r1.y);
            }
        }
    }
}

// ---------------- launch ----------------
extern "C" void kernel_launch(void* const* d_in, const int* in_sizes, int n_in,
                              void* d_out, int out_size){
    const float* x     = (const float*)d_in[0];
    const float* Wq    = (const float*)d_in[1];
    const float* Wk    = (const float*)d_in[2];
    const float* Wv    = (const float*)d_in[3];
    const float* E     = (const float*)d_in[4];
    const float* Fm    = (const float*)d_in[5];
    const float* Wo    = (const float*)d_in[6];
    const float* bo    = (const float*)d_in[7];
    const float* ln1_g = (const float*)d_in[8];
    const float* ln1_b = (const float*)d_in[9];
    const float* ln2_g = (const float*)d_in[10];
    const float* ln2_b = (const float*)d_in[11];
    const float* W1    = (const float*)d_in[12];
    const float* b1    = (const float*)d_in[13];
    const float* W2    = (const float*)d_in[14];
    const float* b2    = (const float*)d_in[15];
    float* out = (float*)d_out;

    cudaFuncSetAttribute(gemm_bulk_kernel<0>, cudaFuncAttributeMaxDynamicSharedMemorySize, GEMM_SMEM);
    cudaFuncSetAttribute(gemm_bulk_kernel<1>, cudaFuncAttributeMaxDynamicSharedMemorySize, GEMM_SMEM);

    zero_small_kernel<<<16, 256>>>();
    ln1_kernel<<<ROWS, 256>>>(x, ln1_g, ln1_b);
    colsum_xn_kernel<<<dim3(BATCH, 32), 1024>>>();
    colsum_ef_kernel<<<dim3(2, 16), 64>>>(E, Fm);
    gemv_AAp_kernel<<<dim3(4, BATCH), 256>>>(Wk, Wv);
    compute_u_kernel<<<dim3(BATCH, 64), 256>>>(Wq);
    compute_G_kernel<<<dim3(BATCH, HEADS), 256>>>(Wo);
    attn_apply_kernel<<<ROWS, 256>>>(x, bo, ln2_g, ln2_b);

    pack_w_kernel<<<(DIMN*MLPD/8 + 255)/256, 256>>>(W1, g_w1p, DIMN, MLPD);
    pack_w_kernel<<<(MLPD*DIMN/8 + 255)/256, 256>>>(W2, g_w2p, MLPD, DIMN);

    gemm_bulk_kernel<0><<<dim3(MLPD/128, ROWS/128), 256, GEMM_SMEM>>>(b1, nullptr);
    gemm_bulk_kernel<1><<<dim3(DIMN/128, ROWS/128), 256, GEMM_SMEM>>>(b2, out);
}

// round 16
// speedup vs baseline: 2.1256x; 1.2245x over previous
#include <cuda_runtime.h>
#include <cuda_bf16.h>
#include <math.h>
#include <stdint.h>

#define DIMN 1024
#define SEQ 4096
#define BATCH 4
#define HEADS 16
#define DHN 64
#define KPROJ 64
#define MLPD 4096
#define EPSV 1e-5f
#define ROWS (BATCH*SEQ)

// ---------------- scratch (static device globals; allocation-free) ----------------
__device__ float g_xn[ROWS*DIMN];                   // LN1 output
__device__ float g_x2[ROWS*DIMN];                   // x + attn residual
// K-chunked (64-deep planes), pre-swizzled activations: [kc64][ROWS][64] bf16
__device__ __nv_bfloat16 g_xn2[ROWS*DIMN];
__device__ __nv_bfloat16 g_hbuf[(size_t)ROWS*MLPD];
// pre-packed, pre-swizzled weights: [nb][kc64][64][128] bf16 (kc inner => 128-chunks contiguous)
__device__ __nv_bfloat16 g_w1p[DIMN*MLPD];
__device__ __nv_bfloat16 g_w2p[MLPD*DIMN];
__device__ float g_m[BATCH*DIMN];
__device__ float g_A[BATCH*DIMN];
__device__ float g_Ap[BATCH*DIMN];
__device__ float g_u[BATCH*DIMN*HEADS];
__device__ float g_G[BATCH*HEADS*DIMN];
__device__ float g_Bsum[KPROJ];
__device__ float g_Bpsum[KPROJ];

// ---------------- helpers ----------------
__device__ __forceinline__ uint32_t smem_u32(const void* p){
    return (uint32_t)__cvta_generic_to_shared(p);
}
__device__ __forceinline__ void ldsm_x4(uint32_t &r0,uint32_t &r1,uint32_t &r2,uint32_t &r3, uint32_t a){
    asm volatile("ldmatrix.sync.aligned.m8n8.x4.shared.b16 {%0,%1,%2,%3}, [%4];\n"
        : "=r"(r0),"=r"(r1),"=r"(r2),"=r"(r3) : "r"(a));
}
__device__ __forceinline__ void ldsm_x4_t(uint32_t &r0,uint32_t &r1,uint32_t &r2,uint32_t &r3, uint32_t a){
    asm volatile("ldmatrix.sync.aligned.m8n8.x4.trans.shared.b16 {%0,%1,%2,%3}, [%4];\n"
        : "=r"(r0),"=r"(r1),"=r"(r2),"=r"(r3) : "r"(a));
}
__device__ __forceinline__ void mma_bf16(float c[4], uint32_t a0,uint32_t a1,uint32_t a2,uint32_t a3,
                                         uint32_t b0,uint32_t b1){
    asm volatile("mma.sync.aligned.m16n8k16.row.col.f32.bf16.bf16.f32 "
        "{%0,%1,%2,%3},{%4,%5,%6,%7},{%8,%9},{%0,%1,%2,%3};\n"
        : "+f"(c[0]),"+f"(c[1]),"+f"(c[2]),"+f"(c[3])
        : "r"(a0),"r"(a1),"r"(a2),"r"(a3),"r"(b0),"r"(b1));
}
__device__ __forceinline__ float gelu_exact(float v){
    return 0.5f*v*(1.0f+erff(v*0.70710678118654752f));
}
__device__ __forceinline__ void mbar_init(uint32_t mbar, uint32_t cnt){
    asm volatile("mbarrier.init.shared.b64 [%0], %1;" :: "r"(mbar), "r"(cnt) : "memory");
}
__device__ __forceinline__ void mbar_expect_tx(uint32_t mbar, uint32_t bytes){
    asm volatile("mbarrier.arrive.expect_tx.shared.b64 _, [%0], %1;"
        :: "r"(mbar), "r"(bytes) : "memory");
}
__device__ __forceinline__ void bulk_g2s(uint32_t dst, const void* src, uint32_t bytes, uint32_t mbar){
    asm volatile("cp.async.bulk.shared::cluster.global.mbarrier::complete_tx::bytes [%0], [%1], %2, [%3];"
        :: "r"(dst), "l"(src), "r"(bytes), "r"(mbar) : "memory");
}
__device__ __forceinline__ void mbar_wait(uint32_t mbar, uint32_t parity){
    asm volatile("{\n\t.reg .pred P;\n"
        "WLP%=:\n\tmbarrier.try_wait.parity.acquire.cta.shared::cta.b64 P, [%0], %1, 0x989680;\n"
        "\t@P bra WDN%=;\n\tbra WLP%=;\nWDN%=:\n\t}"
        :: "r"(mbar), "r"(parity) : "memory");
}
#define FENCE_ASYNC() asm volatile("fence.proxy.async.shared::cta;" ::: "memory")

// ---------------- small kernels ----------------
__global__ void zero_small_kernel(){
    int i = blockIdx.x*256 + threadIdx.x;
    if (i < BATCH*DIMN){ g_m[i] = 0.f; g_A[i] = 0.f; g_Ap[i] = 0.f; }
    if (i < KPROJ){ g_Bsum[i]=0.f; g_Bpsum[i]=0.f; }
}

__global__ __launch_bounds__(256) void ln1_kernel(const float* __restrict__ x,
        const float* __restrict__ g, const float* __restrict__ b){
    int row = blockIdx.x; int tid = threadIdx.x;
    __shared__ float sred[512];
    float4 v = ((const float4*)(x + (size_t)row*DIMN))[tid];
    float s  = v.x+v.y+v.z+v.w;
    float sq = v.x*v.x+v.y*v.y+v.z*v.z+v.w*v.w;
    sred[tid]=s; sred[256+tid]=sq; __syncthreads();
    #pragma unroll
    for (int off=128; off; off>>=1){
        if (tid<off){ sred[tid]+=sred[tid+off]; sred[256+tid]+=sred[256+tid+off]; }
        __syncthreads();
    }
    float mu  = sred[0]*(1.0f/DIMN);
    float var = sred[256]*(1.0f/DIMN) - mu*mu;
    float rs  = rsqrtf(var + EPSV);
    float4 gv = ((const float4*)g)[tid];
    float4 bv = ((const float4*)b)[tid];
    float4 o;
    o.x=(v.x-mu)*rs*gv.x+bv.x; o.y=(v.y-mu)*rs*gv.y+bv.y;
    o.z=(v.z-mu)*rs*gv.z+bv.z; o.w=(v.w-mu)*rs*gv.w+bv.w;
    ((float4*)(g_xn + (size_t)row*DIMN))[tid] = o;
}

// m[b][j] = sum_s xn[b][s][j]; grid (4, 64), block 1024, 64 rows per block
__global__ void colsum_xn_kernel(){
    int b = blockIdx.x, chunk = blockIdx.y, j = threadIdx.x;
    const float* base = g_xn + ((size_t)(b*SEQ + chunk*64))*DIMN + j;
    float acc = 0.f;
    #pragma unroll 4
    for (int s=0; s<64; s++) acc += base[(size_t)s*DIMN];
    atomicAdd(&g_m[b*DIMN + j], acc);
}

// column sums of E, Fm; grid (2, 128), block 64, 32 rows per block
__global__ void colsum_ef_kernel(const float* __restrict__ E, const float* __restrict__ Fm){
    const float* src = blockIdx.x ? Fm : E;
    float* dst = blockIdx.x ? g_Bpsum : g_Bsum;
    int kk = threadIdx.x;
    int s0 = blockIdx.y*32;
    float acc = 0.f;
    #pragma unroll 4
    for (int s=0; s<32; s++) acc += src[(size_t)(s0+s)*KPROJ + kk];
    atomicAdd(&dst[kk], acc);
}

// A = m@Wk, A' = m@Wv ; grid (4 colchunk, 4 b, 4 jchunk), block 256, atomic accumulate
__global__ __launch_bounds__(256) void gemv_AAp_kernel(const float* __restrict__ Wk,
        const float* __restrict__ Wv){
    int b = blockIdx.y;
    int col = blockIdx.x*256 + threadIdx.x;
    int j0 = blockIdx.z*256;
    __shared__ float sm[256];
    sm[threadIdx.x] = g_m[b*DIMN + j0 + threadIdx.x];
    __syncthreads();
    float ak=0.f, av=0.f;
    for (int j=0; j<256; j++){
        float mj = sm[j];
        ak += mj * Wk[(size_t)(j0+j)*DIMN + col];
        av += mj * Wv[(size_t)(j0+j)*DIMN + col];
    }
    atomicAdd(&g_A [b*DIMN + col], ak);
    atomicAdd(&g_Ap[b*DIMN + col], av);
}

__global__ __launch_bounds__(256) void compute_u_kernel(const float* __restrict__ Wq){
    int b = blockIdx.x;
    __shared__ float sA[DIMN];
    for (int i=threadIdx.x; i<DIMN; i+=256) sA[i] = g_A[b*DIMN + i];
    __syncthreads();
    int j = blockIdx.y*16 + (threadIdx.x >> 4);
    int h = threadIdx.x & 15;
    const float* wrow = Wq + (size_t)j*DIMN + h*DHN;
    const float* av = sA + h*DHN;
    float acc = 0.f;
    #pragma unroll
    for (int d=0; d<DHN; d++) acc += wrow[d]*av[d];
    g_u[((size_t)b*DIMN + j)*HEADS + h] = acc;
}

__global__ __launch_bounds__(256) void compute_G_kernel(const float* __restrict__ Wo){
    int b = blockIdx.x, h = blockIdx.y;
    __shared__ float sa[DHN];
    if (threadIdx.x < DHN) sa[threadIdx.x] = g_Ap[b*DIMN + h*DHN + threadIdx.x];
    __syncthreads();
    float4 acc = {0.f,0.f,0.f,0.f};
    #pragma unroll 8
    for (int d=0; d<DHN; d++){
        float a = sa[d];
        float4 w = ((const float4*)(Wo + (size_t)(h*DHN + d)*DIMN))[threadIdx.x];
        acc.x += a*w.x; acc.y += a*w.y; acc.z += a*w.z; acc.w += a*w.w;
    }
    ((float4*)(g_G + (size_t)(b*HEADS + h)*DIMN))[threadIdx.x] = acc;
}

// fused attn + residual + LN2; writes xn2 bf16 in K-chunked swizzled layout
__global__ __launch_bounds__(256) void attn_apply_kernel(const float* __restrict__ x,
        const float* __restrict__ bo, const float* __restrict__ g2, const float* __restrict__ b2){
    int row = blockIdx.x;
    int b = row / SEQ;
    int tid = threadIdx.x;
    __shared__ float sxn[DIMN];
    __shared__ float sred[512];
    __shared__ float sw[HEADS];
    __shared__ float sB[KPROJ], sBp[KPROJ];

    ((float4*)sxn)[tid] = ((const float4*)(g_xn + (size_t)row*DIMN))[tid];
    if (tid < KPROJ){ sB[tid]=g_Bsum[tid]; sBp[tid]=g_Bpsum[tid]; }
    __syncthreads();

    int h = tid & 15, grp = tid >> 4;
    const float* ub = g_u + (size_t)b*DIMN*HEADS;
    float acc = 0.f;
    for (int jj = grp; jj < DIMN; jj += 16) acc += sxn[jj] * ub[(size_t)jj*HEADS + h];
    sred[tid] = acc;
    __syncthreads();
    #pragma unroll
    for (int off=128; off>=16; off>>=1){
        if (tid < off) sred[tid] += sred[tid+off];
        __syncthreads();
    }
    if (tid < HEADS){
        float c = sred[tid] * 0.125f;
        float mx = -INFINITY;
        #pragma unroll 8
        for (int k2=0; k2<KPROJ; k2++) mx = fmaxf(mx, c*sB[k2]);
        float se=0.f, sv=0.f;
        for (int k2=0; k2<KPROJ; k2++){
            float e = expf(c*sB[k2]-mx);
            se += e; sv += e*sBp[k2];
        }
        sw[tid] = sv/se;
    }
    __syncthreads();

    float4 xv = ((const float4*)(x + (size_t)row*DIMN))[tid];
    float4 bov = ((const float4*)bo)[tid];
    float4 o = {xv.x+bov.x, xv.y+bov.y, xv.z+bov.z, xv.w+bov.w};
    const float* Gb = g_G + (size_t)b*HEADS*DIMN;
    #pragma unroll
    for (int hh=0; hh<HEADS; hh++){
        float w = sw[hh];
        float4 g4 = ((const float4*)(Gb + (size_t)hh*DIMN))[tid];
        o.x += w*g4.x; o.y += w*g4.y; o.z += w*g4.z; o.w += w*g4.w;
    }
    ((float4*)(g_x2 + (size_t)row*DIMN))[tid] = o;

    float s  = o.x+o.y+o.z+o.w;
    float sq = o.x*o.x+o.y*o.y+o.z*o.z+o.w*o.w;
    sred[tid]=s; sred[256+tid]=sq; __syncthreads();
    #pragma unroll
    for (int off=128; off; off>>=1){
        if (tid<off){ sred[tid]+=sred[tid+off]; sred[256+tid]+=sred[256+tid+off]; }
        __syncthreads();
    }
    float mu  = sred[0]*(1.0f/DIMN);
    float var = sred[256]*(1.0f/DIMN) - mu*mu;
    float rs  = rsqrtf(var + EPSV);
    float4 gv = ((const float4*)g2)[tid];
    float4 b2v = ((const float4*)b2)[tid];
    float v0=(o.x-mu)*rs*gv.x+b2v.x, v1=(o.y-mu)*rs*gv.y+b2v.y;
    float v2=(o.z-mu)*rs*gv.z+b2v.z, v3=(o.w-mu)*rs*gv.w+b2v.w;

    // chunked + swizzled write
    int c0 = tid*4;
    int kc = c0 >> 6, cc = c0 & 63, g = cc >> 3;
    int gp = g ^ (row & 7);
    uint2 val;
    __nv_bfloat162 p0 = __floats2bfloat162_rn(v0, v1);
    __nv_bfloat162 p1 = __floats2bfloat162_rn(v2, v3);
    val.x = *(uint32_t*)&p0; val.y = *(uint32_t*)&p1;
    *(uint2*)((char*)g_xn2 + ((size_t)kc*ROWS + row)*128 + gp*16 + (cc & 7)*2) = val;
}

// pack W [K][N] fp32 -> [nb][kc64][kr 0..63][128 cols swizzled] bf16
__global__ __launch_bounds__(256) void pack_w_kernel(const float* __restrict__ src,
        __nv_bfloat16* __restrict__ dst, int Kdim, int Ndim){
    int t = blockIdx.x*256 + threadIdx.x;          // one 8-elem granule
    int KCn = Kdim >> 6;
    int g  = t & 15;
    int kr = (t >> 4) & 63;
    int rest = t >> 10;         // nb*KCn + kc
    int kc = rest % KCn;
    int nb = rest / KCn;
    if (nb >= (Ndim >> 7)) return;
    int k = kc*64 + kr;
    int n = nb*128 + g*8;
    const float* s = src + (size_t)k*Ndim + n;
    float4 v0 = *(const float4*)s;
    float4 v1 = *(const float4*)(s+4);
    int gp = (g & 8) | ((g & 7) ^ (kr & 7));
    __nv_bfloat162* d = (__nv_bfloat162*)(dst + ((((size_t)rest)*64 + kr)*128) + gp*8);
    d[0] = __floats2bfloat162_rn(v0.x, v0.y);
    d[1] = __floats2bfloat162_rn(v0.z, v0.w);
    d[2] = __floats2bfloat162_rn(v1.x, v1.y);
    d[3] = __floats2bfloat162_rn(v1.z, v1.w);
}

// ---------- bf16 mma GEMM, 128x128 tile, KC=128, bulk-copy 3-stage mbarrier ring ----------
#define GST 3
#define ASUB_B (128*128)               // 16 KB per 64-deep A sub-plane
#define ATILE_B (2*ASUB_B)             // 32 KB (two kc64 planes)
#define BTILE_B (128*256)              // 32 KB (two contiguous kc64 blocks)
#define STAGE_B (ATILE_B + BTILE_B)    // 64 KB
#define GEMM_SMEM (GST*STAGE_B + 64)   // 196672 B

template<int MODE>
__global__ __launch_bounds__(256,1) void gemm_bulk_kernel(const float* __restrict__ bias,
                                                          float* __restrict__ Cf){
    constexpr int N  = (MODE==0) ? MLPD : DIMN;
    constexpr int K  = (MODE==0) ? DIMN : MLPD;
    constexpr int nk = K / 128;                        // 128-deep chunks
    const __nv_bfloat16* Ach = (MODE==0) ? g_xn2 : g_hbuf;   // [kc64][ROWS][64]
    const __nv_bfloat16* Bpk = (MODE==0) ? g_w1p : g_w2p;    // [nb][kc64][64][128]

    extern __shared__ __align__(128) char smem[];
    uint32_t sbase = smem_u32(smem);
    uint32_t mbar  = sbase + GST*STAGE_B;
    int tid = threadIdx.x, warp = tid >> 5, lane = tid & 31;
    int bm = blockIdx.y * 128;
    int nb = blockIdx.x;
    int wm = (warp >> 2) * 64;
    int wn = (warp & 3) * 32;

    if (tid == 0){
        #pragma unroll
        for (int s=0; s<GST; s++) mbar_init(mbar + 8*s, 1);
        FENCE_ASYNC();
    }
    __syncthreads();

    auto fill = [&](int st, int kc){       // kc = 128-deep chunk index
        uint32_t dstA = sbase + st*STAGE_B;
        uint32_t mb = mbar + 8*st;
        mbar_expect_tx(mb, STAGE_B);
        bulk_g2s(dstA,          (const char*)Ach + ((size_t)(2*kc  )*ROWS + bm)*128, ASUB_B, mb);
        bulk_g2s(dstA + ASUB_B, (const char*)Ach + ((size_t)(2*kc+1)*ROWS + bm)*128, ASUB_B, mb);
        bulk_g2s(dstA + ATILE_B,
                 (const char*)Bpk + ((size_t)nb*(2*nk) + 2*kc)*(size_t)(64*256), BTILE_B, mb);
    };

    if (tid == 0){
        fill(0, 0);
        if (nk > 1) fill(1, 1);
    }

    float acc[4][4][4];
    #pragma unroll
    for (int i=0;i<4;i++)
        #pragma unroll
        for (int j=0;j<4;j++)
            #pragma unroll
            for (int k=0;k<4;k++) acc[i][j][k]=0.f;

    for (int kt = 0; kt < nk; kt++){
        int cur = kt % GST;
        __syncthreads();                   // all threads finished reading stage (kt-1)%GST
        if (tid == 0 && kt + GST - 1 < nk) fill((kt + GST - 1) % GST, kt + GST - 1);
        mbar_wait(mbar + 8*cur, (kt / GST) & 1);

        uint32_t As = sbase + cur*STAGE_B;
        uint32_t Bs = As + ATILE_B;

        #pragma unroll
        for (int ks=0; ks<8; ks++){
            uint32_t asub = As + ((ks >> 2) ? ASUB_B : 0);
            int ksl = ks & 3;
            uint32_t af[4][4], bfr[4][2];
            #pragma unroll
            for (int mi=0; mi<4; mi++){
                int r = wm + mi*16 + (lane & 15);
                int g = ksl*2 + (lane >> 4);
                int gp = g ^ (r & 7);
                ldsm_x4(af[mi][0],af[mi][1],af[mi][2],af[mi][3],
                        asub + r*128 + gp*16);
            }
            #pragma unroll
            for (int nj=0; nj<2; nj++){
                int r = ks*16 + (((lane>>3)&1) << 3) + (lane & 7);
                int c = wn + nj*16 + ((lane >> 4) << 3);
                int g = c >> 3;
                int gp = (g & 8) | ((g & 7) ^ (r & 7));
                uint32_t t0,t1,t2,t3;
                ldsm_x4_t(t0,t1,t2,t3, Bs + r*256 + gp*16);
                bfr[nj*2][0]=t0; bfr[nj*2][1]=t1;
                bfr[nj*2+1][0]=t2; bfr[nj*2+1][1]=t3;
            }
            #pragma unroll
            for (int mi=0; mi<4; mi++)
                #pragma unroll
                for (int ni=0; ni<4; ni++)
                    mma_bf16(acc[mi][ni], af[mi][0],af[mi][1],af[mi][2],af[mi][3],
                             bfr[ni][0], bfr[ni][1]);
        }
    }

    // epilogue
    #pragma unroll
    for (int mi=0; mi<4; mi++){
        #pragma unroll
        for (int ni=0; ni<4; ni++){
            int r = bm + wm + mi*16 + (lane >> 2);
            int c = nb*128 + wn + ni*8 + (lane & 3)*2;
            float* a = acc[mi][ni];
            float bx = bias[c], by = bias[c+1];
            if (MODE == 0){
                float v0 = gelu_exact(a[0]+bx), v1 = gelu_exact(a[1]+by);
                float v2 = gelu_exact(a[2]+bx), v3 = gelu_exact(a[3]+by);
                int kc = c >> 6, cc = c & 63, g = cc >> 3;
                int gp = g ^ (r & 7);      // (r+8)&7 == r&7
                size_t base0 = ((size_t)kc*ROWS + r)*128 + gp*16 + (cc & 7)*2;
                __nv_bfloat162 p0 = __floats2bfloat162_rn(v0, v1);
                __nv_bfloat162 p1 = __floats2bfloat162_rn(v2, v3);
                *(__nv_bfloat162*)((char*)g_hbuf + base0)         = p0;
                *(__nv_bfloat162*)((char*)g_hbuf + base0 + 8*128) = p1;
            } else {
                size_t o0 = (size_t)r*N + c, o1 = (size_t)(r+8)*N + c;
                float2 r0 = *(const float2*)(g_x2 + o0);
                float2 r1 = *(const float2*)(g_x2 + o1);
                *(float2*)(Cf + o0) = make_float2(a[0]+bx+r0.x, a[1]+by+r0.y);
                *(float2*)(Cf + o1) = make_float2(a[2]+bx+r1.x, a[3]+by+r1.y);
            }
        }
    }
}

// ---------------- launch ----------------
extern "C" void kernel_launch(void* const* d_in, const int* in_sizes, int n_in,
                              void* d_out, int out_size){
    const float* x     = (const float*)d_in[0];
    const float* Wq    = (const float*)d_in[1];
    const float* Wk    = (const float*)d_in[2];
    const float* Wv    = (const float*)d_in[3];
    const float* E     = (const float*)d_in[4];
    const float* Fm    = (const float*)d_in[5];
    const float* Wo    = (const float*)d_in[6];
    const float* bo    = (const float*)d_in[7];
    const float* ln1_g = (const float*)d_in[8];
    const float* ln1_b = (const float*)d_in[9];
    const float* ln2_g = (const float*)d_in[10];
    const float* ln2_b = (const float*)d_in[11];
    const float* W1    = (const float*)d_in[12];
    const float* b1    = (const float*)d_in[13];
    const float* W2    = (const float*)d_in[14];
    const float* b2    = (const float*)d_in[15];
    float* out = (float*)d_out;

    cudaFuncSetAttribute(gemm_bulk_kernel<0>, cudaFuncAttributeMaxDynamicSharedMemorySize, GEMM_SMEM);
    cudaFuncSetAttribute(gemm_bulk_kernel<1>, cudaFuncAttributeMaxDynamicSharedMemorySize, GEMM_SMEM);

    zero_small_kernel<<<16, 256>>>();
    ln1_kernel<<<ROWS, 256>>>(x, ln1_g, ln1_b);
    colsum_xn_kernel<<<dim3(BATCH, 64), 1024>>>();
    colsum_ef_kernel<<<dim3(2, 128), 64>>>(E, Fm);
    gemv_AAp_kernel<<<dim3(4, BATCH, 4), 256>>>(Wk, Wv);
    compute_u_kernel<<<dim3(BATCH, 64), 256>>>(Wq);
    compute_G_kernel<<<dim3(BATCH, HEADS), 256>>>(Wo);
    attn_apply_kernel<<<ROWS, 256>>>(x, bo, ln2_g, ln2_b);

    pack_w_kernel<<<(DIMN*MLPD/8 + 255)/256, 256>>>(W1, g_w1p, DIMN, MLPD);
    pack_w_kernel<<<(MLPD*DIMN/8 + 255)/256, 256>>>(W2, g_w2p, MLPD, DIMN);

    gemm_bulk_kernel<0><<<dim3(MLPD/128, ROWS/128), 256, GEMM_SMEM>>>(b1, nullptr);
    gemm_bulk_kernel<1><<<dim3(DIMN/128, ROWS/128), 256, GEMM_SMEM>>>(b2, out);
}